// round 1
// baseline (speedup 1.0000x reference)
#include <cuda_runtime.h>
#include <math.h>

#define NB 4
#define NS 256
#define ND 300
#define NM (NB*NS)   // 1024 rows
#define NK 300
#define N3 (3*ND)    // 900: dep | head(+b1) | g1(+b_f)
#define CC 5.0f

// Scratch (static device globals — no allocation allowed)
__device__ float g_rep[NM*ND];
__device__ float g_dhg[NM*N3];
__device__ float g_attn[NM*ND];

// ---------------- GEMM config: BM=BN=64, BK=16, TM=TN=4, 256 thr ----------------
#define BM 64
#define BN 64
#define BK 16

// rep_map = elu(inputs @ W_fc^T + b_fc)
__global__ void __launch_bounds__(256)
gemm_rep_kernel(const float* __restrict__ A, const float* __restrict__ W,
                const float* __restrict__ bias)
{
    __shared__ __align__(16) float As[BK][BM+4];
    __shared__ __align__(16) float Bs[BK][BN+4];
    const int tid = threadIdx.x;
    const int tx = tid & 15, ty = tid >> 4;
    const int m0 = blockIdx.y * BM, n0 = blockIdx.x * BN;
    float acc[4][4] = {};
    for (int k0 = 0; k0 < NK; k0 += BK) {
        #pragma unroll
        for (int i = tid; i < BM*BK; i += 256) {
            int r = i >> 4, c = i & 15;
            int gk = k0 + c;
            As[c][r] = (gk < NK) ? A[(m0 + r)*NK + gk] : 0.f;
        }
        #pragma unroll
        for (int i = tid; i < BN*BK; i += 256) {
            int r = i >> 4, c = i & 15;
            int gk = k0 + c, gn = n0 + r;
            Bs[c][r] = (gk < NK && gn < ND) ? W[gn*NK + gk] : 0.f;
        }
        __syncthreads();
        #pragma unroll
        for (int k = 0; k < BK; ++k) {
            const float4 af = *(const float4*)&As[k][ty*4];
            const float4 bf = *(const float4*)&Bs[k][tx*4];
            float a[4] = {af.x, af.y, af.z, af.w};
            float bb[4] = {bf.x, bf.y, bf.z, bf.w};
            #pragma unroll
            for (int p = 0; p < 4; ++p)
                #pragma unroll
                for (int q = 0; q < 4; ++q)
                    acc[p][q] = fmaf(a[p], bb[q], acc[p][q]);
        }
        __syncthreads();
    }
    #pragma unroll
    for (int p = 0; p < 4; ++p) {
        int m = m0 + ty*4 + p;
        #pragma unroll
        for (int q = 0; q < 4; ++q) {
            int n = n0 + tx*4 + q;
            if (n < ND) {
                float v = acc[p][q] + bias[n];
                g_rep[m*ND + n] = (v > 0.f) ? v : expm1f(v);
            }
        }
    }
}

// g_dhg[:,0:300]=rep@W1^T ; [:,300:600]=rep@W2^T+b1 ; [:,600:900]=rep@W_f1^T+b_f
__global__ void __launch_bounds__(256)
gemm_triple_kernel(const float* __restrict__ Wd, const float* __restrict__ Wh,
                   const float* __restrict__ Wg, const float* __restrict__ b1,
                   const float* __restrict__ bf)
{
    __shared__ __align__(16) float As[BK][BM+4];
    __shared__ __align__(16) float Bs[BK][BN+4];
    const int tid = threadIdx.x;
    const int tx = tid & 15, ty = tid >> 4;
    const int m0 = blockIdx.y * BM, n0 = blockIdx.x * BN;
    float acc[4][4] = {};
    for (int k0 = 0; k0 < NK; k0 += BK) {
        #pragma unroll
        for (int i = tid; i < BM*BK; i += 256) {
            int r = i >> 4, c = i & 15;
            int gk = k0 + c;
            As[c][r] = (gk < NK) ? g_rep[(m0 + r)*NK + gk] : 0.f;
        }
        #pragma unroll
        for (int i = tid; i < BN*BK; i += 256) {
            int r = i >> 4, c = i & 15;
            int gk = k0 + c, gn = n0 + r;
            float v = 0.f;
            if (gk < NK && gn < N3) {
                int mat = gn / ND;
                int nn  = gn - mat*ND;
                const float* Wp = (mat == 0) ? Wd : ((mat == 1) ? Wh : Wg);
                v = Wp[nn*NK + gk];
            }
            Bs[c][r] = v;
        }
        __syncthreads();
        #pragma unroll
        for (int k = 0; k < BK; ++k) {
            const float4 af = *(const float4*)&As[k][ty*4];
            const float4 bf4 = *(const float4*)&Bs[k][tx*4];
            float a[4] = {af.x, af.y, af.z, af.w};
            float bb[4] = {bf4.x, bf4.y, bf4.z, bf4.w};
            #pragma unroll
            for (int p = 0; p < 4; ++p)
                #pragma unroll
                for (int q = 0; q < 4; ++q)
                    acc[p][q] = fmaf(a[p], bb[q], acc[p][q]);
        }
        __syncthreads();
    }
    #pragma unroll
    for (int p = 0; p < 4; ++p) {
        int m = m0 + ty*4 + p;
        #pragma unroll
        for (int q = 0; q < 4; ++q) {
            int n = n0 + tx*4 + q;
            if (n < N3) {
                int mat = n / ND;
                int nn  = n - mat*ND;
                float v = acc[p][q];
                if (mat == 1) v += b1[nn];
                else if (mat == 2) v += bf[nn];
                g_dhg[m*N3 + n] = v;
            }
        }
    }
}

// Attention: per (b,i), softmax over valid j of C*tanh((dep[j]+head[i]+b1)/C),
// then attn_result[b,i,d] = sum_j attn * rep_map[b,j,d].
// Single-pass (no max needed: logits bounded in [-C,C]); exact softmax algebra.
__global__ void __launch_bounds__(320)
attn_kernel(const int* __restrict__ rmask)
{
    const int b = blockIdx.y;
    const int i = blockIdx.x;
    const int t = threadIdx.x;

    __shared__ int jlist[NS];
    __shared__ int wcnt[8];
    __shared__ int nvalid_s;

    // deterministic warp-ballot compaction of valid j (j > i && rep_mask[b,j])
    bool v = false;
    unsigned bal = 0;
    if (t < NS) {
        v = (t > i) && (rmask[b*NS + t] != 0);
        bal = __ballot_sync(0xFFFFFFFFu, v);
        if ((t & 31) == 0) wcnt[t >> 5] = __popc(bal);
    }
    __syncthreads();
    if (t == 0) {
        int a = 0;
        #pragma unroll
        for (int k = 0; k < 8; ++k) { int c = wcnt[k]; wcnt[k] = a; a += c; }
        nvalid_s = a;
    }
    __syncthreads();
    if (t < NS && v) {
        int pos = wcnt[t >> 5] + __popc(bal & ((1u << (t & 31)) - 1u));
        jlist[pos] = t;
    }
    __syncthreads();

    const int nvalid = nvalid_s;
    if (t >= ND) return;

    const float hb = g_dhg[(size_t)(b*NS + i)*N3 + ND + t];  // head + b1
    const float* __restrict__ dep_base = g_dhg + (size_t)(b*NS)*N3 + t;
    const float* __restrict__ rep_base = g_rep + (size_t)(b*NS)*ND + t;

    float s = 0.f, w = 0.f;
    for (int idx = 0; idx < nvalid; ++idx) {
        int j = jlist[idx];
        float dj = dep_base[j*N3];
        float x2 = (dj + hb) * (2.0f / CC);
        float e2 = __expf(x2);
        float th = __fdividef(e2 - 1.f, e2 + 1.f);
        float l  = CC * th;
        float e  = __expf(l);
        s += e;
        w = fmaf(e, rep_base[j*ND], w);
    }
    float denom = s + ((s == 0.f) ? 1.f : 0.f) + 1e-20f;
    g_attn[(size_t)(b*NS + i)*ND + t] = w / denom;
}

// Final: gate = sigmoid(g1 + attn@W_f2^T) (b_f already folded into g1);
// out = (gate*rep + (1-gate)*attn) * rep_mask
__global__ void __launch_bounds__(256)
gemm_final_kernel(const float* __restrict__ Wf2, const int* __restrict__ rmask,
                  float* __restrict__ out)
{
    __shared__ __align__(16) float As[BK][BM+4];
    __shared__ __align__(16) float Bs[BK][BN+4];
    const int tid = threadIdx.x;
    const int tx = tid & 15, ty = tid >> 4;
    const int m0 = blockIdx.y * BM, n0 = blockIdx.x * BN;
    float acc[4][4] = {};
    for (int k0 = 0; k0 < NK; k0 += BK) {
        #pragma unroll
        for (int i = tid; i < BM*BK; i += 256) {
            int r = i >> 4, c = i & 15;
            int gk = k0 + c;
            As[c][r] = (gk < NK) ? g_attn[(m0 + r)*NK + gk] : 0.f;
        }
        #pragma unroll
        for (int i = tid; i < BN*BK; i += 256) {
            int r = i >> 4, c = i & 15;
            int gk = k0 + c, gn = n0 + r;
            Bs[c][r] = (gk < NK && gn < ND) ? Wf2[gn*NK + gk] : 0.f;
        }
        __syncthreads();
        #pragma unroll
        for (int k = 0; k < BK; ++k) {
            const float4 af = *(const float4*)&As[k][ty*4];
            const float4 bf = *(const float4*)&Bs[k][tx*4];
            float a[4] = {af.x, af.y, af.z, af.w};
            float bb[4] = {bf.x, bf.y, bf.z, bf.w};
            #pragma unroll
            for (int p = 0; p < 4; ++p)
                #pragma unroll
                for (int q = 0; q < 4; ++q)
                    acc[p][q] = fmaf(a[p], bb[q], acc[p][q]);
        }
        __syncthreads();
    }
    #pragma unroll
    for (int p = 0; p < 4; ++p) {
        int m = m0 + ty*4 + p;
        float mf = (float)rmask[m];
        #pragma unroll
        for (int q = 0; q < 4; ++q) {
            int n = n0 + tx*4 + q;
            if (n < ND) {
                float vv = acc[p][q] + g_dhg[m*N3 + 2*ND + n];
                float gate = 1.f / (1.f + __expf(-vv));
                float r = g_rep[m*ND + n];
                float a = g_attn[m*ND + n];
                out[m*ND + n] = (gate*r + (1.f - gate)*a) * mf;
            }
        }
    }
}

extern "C" void kernel_launch(void* const* d_in, const int* in_sizes, int n_in,
                              void* d_out, int out_size)
{
    const float* inputs = (const float*)d_in[0];
    const int*   rmask  = (const int*)d_in[1];
    const float* W_fc   = (const float*)d_in[2];
    const float* b_fc   = (const float*)d_in[3];
    const float* W1     = (const float*)d_in[4];
    const float* W2     = (const float*)d_in[5];
    const float* b1     = (const float*)d_in[6];
    const float* W_f1   = (const float*)d_in[7];
    const float* W_f2   = (const float*)d_in[8];
    const float* b_f    = (const float*)d_in[9];
    float* out = (float*)d_out;

    dim3 blk(256);
    dim3 g300((ND + BN - 1)/BN, NM/BM);   // (5, 16)
    dim3 g900((N3 + BN - 1)/BN, NM/BM);   // (15, 16)

    gemm_rep_kernel<<<g300, blk>>>(inputs, W_fc, b_fc);
    gemm_triple_kernel<<<g900, blk>>>(W1, W2, W_f1, b1, b_f);
    attn_kernel<<<dim3(NS, NB), 320>>>(rmask);
    gemm_final_kernel<<<g300, blk>>>(W_f2, rmask, out);
}